// round 16
// baseline (speedup 1.0000x reference)
#include <cuda_runtime.h>
#include <cuda_bf16.h>
#include <mma.h>
#include <cstdint>

using namespace nvcuda;

#define NN 50000
#define EE 800000
#define C3 384
#define HID 128
#define OUTC 40
#define OPAD 48
#define FP 400            // g_f row stride (384 feat + 3 el + 3 er + pad to store-tile)
#define BN_EPS 1e-5f
#define SLOPE 0.2f

// ---------------- scratch ----------------
__device__ __align__(128) float g_f[(size_t)NN * FP];
__device__ __align__(128) float g_h[(size_t)NN * C3];
__device__ __align__(128) float g_out[(size_t)NN * C3];
__device__ __align__(128) float g_wp0[HID * FP];      // W0 + attn cols, tf32
__device__ __align__(128) float g_wp1[C3 * FP];
__device__ __align__(128) float g_wp2[C3 * OPAD];
__device__ __align__(128) float g_e[(size_t)EE * 3];
__device__ __align__(128) float g_bns[2][C3];
__device__ __align__(128) float g_bnq[2][C3];
__device__ __align__(128) int g_cnt[NN];
__device__ __align__(128) int g_off[NN + 1];
__device__ __align__(128) int g_cur[NN];
__device__ __align__(128) int g_eidx[EE];

// side stream + fork/join events (host objects only, created once)
struct SideStream {
    cudaStream_t s = nullptr;
    cudaEvent_t fork = nullptr, join_csr = nullptr, join_w0 = nullptr;
    SideStream() {
        cudaStreamCreateWithFlags(&s, cudaStreamNonBlocking);
        cudaEventCreateWithFlags(&fork, cudaEventDisableTiming);
        cudaEventCreateWithFlags(&join_csr, cudaEventDisableTiming);
        cudaEventCreateWithFlags(&join_w0, cudaEventDisableTiming);
    }
};
static SideStream g_ss;

__device__ __forceinline__ float lrelu(float v) { return v > 0.f ? v : SLOPE * v; }
__device__ __forceinline__ float wmaxf(float v) {
#pragma unroll
    for (int o = 16; o; o >>= 1) v = fmaxf(v, __shfl_xor_sync(0xffffffffu, v, o));
    return v;
}
__device__ __forceinline__ float wsumf(float v) {
#pragma unroll
    for (int o = 16; o; o >>= 1) v += __shfl_xor_sync(0xffffffffu, v, o);
    return v;
}
__device__ __forceinline__ void cp16(void* dst, const void* src, bool pred) {
    uint32_t d = (uint32_t)__cvta_generic_to_shared(dst);
    int sz = pred ? 16 : 0;
    asm volatile("cp.async.cg.shared.global [%0], [%1], 16, %2;\n"
                 :: "r"(d), "l"(src), "r"(sz));
}

// ---------------- tf32 rounding ----------------
__global__ void round_tf32(const float* __restrict__ in, float* __restrict__ out, int n4) {
    int i = blockIdx.x * blockDim.x + threadIdx.x;
    if (i >= n4) return;
    float4 v = ((const float4*)in)[i];
    v.x = wmma::__float_to_tf32(v.x);
    v.y = wmma::__float_to_tf32(v.y);
    v.z = wmma::__float_to_tf32(v.z);
    v.w = wmma::__float_to_tf32(v.w);
    ((float4*)out)[i] = v;
}
// padded weight with folded attention columns:
// out[k, c] = tf32( c<Nw ? W[k,c] : c<Nw+nh ? W[k,hd..]·al[h] : c<Nw+2nh ? W[k,hd..]·ar[h] : 0 )
__global__ void wprep(const float* __restrict__ W, const float* __restrict__ al,
                      const float* __restrict__ ar, float* __restrict__ out,
                      int K, int Nw, int NP, int nh, int d) {
    int i = blockIdx.x * blockDim.x + threadIdx.x;
    if (i >= K * NP) return;
    int k = i / NP, c = i - k * NP;
    float v = 0.f;
    if (c < Nw) {
        v = W[(size_t)k * Nw + c];
    } else if (c < Nw + nh) {
        int h = c - Nw;
        float s = 0.f;
        for (int j = 0; j < d; j++) s += W[(size_t)k * Nw + h * d + j] * al[h * d + j];
        v = s;
    } else if (c < Nw + 2 * nh) {
        int h = c - Nw - nh;
        float s = 0.f;
        for (int j = 0; j < d; j++) s += W[(size_t)k * Nw + h * d + j] * ar[h * d + j];
        v = s;
    }
    out[i] = wmma::__float_to_tf32(v);
}

// ---- tf32 GEMM, 3-stage cp.async, 128x64 tile, warp tile 32x32 ---------------------
#define BM 128
#define BNT 64
#define BKK 16
#define APITCH (BKK + 4)
#define BPITCH (BNT + 4)
#define ASTAGE (BM * APITCH)
#define BSTAGE (BKK * BPITCH)

__global__ void __launch_bounds__(256) gemm_tf32(const float* __restrict__ A,
                                                 const float* __restrict__ B,
                                                 float* __restrict__ C,
                                                 int M, int N, int K, int ldc) {
    __shared__ float As[3][ASTAGE];
    __shared__ float Bs[3][BSTAGE];

    const int tid = threadIdx.x;
    const int wid = tid >> 5;
    const int warp_m = wid >> 1;
    const int warp_n = wid & 1;
    const int row0 = blockIdx.y * BM;
    const int col0 = blockIdx.x * BNT;

    wmma::fragment<wmma::accumulator, 16, 16, 8, float> acc[2][2];
#pragma unroll
    for (int i = 0; i < 2; i++)
#pragma unroll
        for (int j = 0; j < 2; j++) wmma::fill_fragment(acc[i][j], 0.f);

    auto load_tile = [&](int k0, int buf) {
        float* Ab = As[buf];
        float* Bb = Bs[buf];
#pragma unroll
        for (int t = 0; t < 2; t++) {
            int idx = tid + t * 256;
            int r = idx >> 2;
            int c4 = (idx & 3) * 4;
            cp16(&Ab[r * APITCH + c4], &A[(size_t)(row0 + r) * K + k0 + c4], (row0 + r) < M);
        }
        {
            int r = tid >> 4;
            int c4 = (tid & 15) * 4;
            cp16(&Bb[r * BPITCH + c4], &B[(size_t)(k0 + r) * N + col0 + c4], (col0 + c4) < N);
        }
        asm volatile("cp.async.commit_group;\n");
    };

    const int KT = K / BKK;
    load_tile(0, 0);
    if (KT > 1) load_tile(BKK, 1);

    int buf = 0;
    for (int kt = 0; kt < KT; kt++) {
        asm volatile("cp.async.wait_group 1;\n");
        __syncthreads();
        float* Ab = As[buf];
        float* Bb = Bs[buf];
#pragma unroll
        for (int kk = 0; kk < BKK; kk += 8) {
            wmma::fragment<wmma::matrix_a, 16, 16, 8, wmma::precision::tf32, wmma::row_major> af[2];
            wmma::fragment<wmma::matrix_b, 16, 16, 8, wmma::precision::tf32, wmma::row_major> bf[2];
#pragma unroll
            for (int i = 0; i < 2; i++)
                wmma::load_matrix_sync(af[i], &Ab[(warp_m * 32 + i * 16) * APITCH + kk], APITCH);
#pragma unroll
            for (int j = 0; j < 2; j++)
                wmma::load_matrix_sync(bf[j], &Bb[kk * BPITCH + warp_n * 32 + j * 16], BPITCH);
#pragma unroll
            for (int i = 0; i < 2; i++)
#pragma unroll
                for (int j = 0; j < 2; j++)
                    wmma::mma_sync(acc[i][j], af[i], bf[j], acc[i][j]);
        }
        if (kt + 2 < KT) load_tile((kt + 2) * BKK, (kt + 2) % 3);
        else asm volatile("cp.async.commit_group;\n");
        buf = (buf + 1) % 3;
    }

#pragma unroll
    for (int i = 0; i < 2; i++) {
        int gr = row0 + warp_m * 32 + i * 16;
        if (gr >= M) continue;
#pragma unroll
        for (int j = 0; j < 2; j++) {
            int gc = col0 + warp_n * 32 + j * 16;
            if (gc + 16 <= ldc)
                wmma::store_matrix_sync(&C[(size_t)gr * ldc + gc], acc[i][j], ldc, wmma::mem_row_major);
        }
    }
}

// ---------------- CSR build (+ BN accumulator zeroing, both slots) ----------------
__global__ void csr_zero() {
    int i = blockIdx.x * blockDim.x + threadIdx.x;
    if (i < NN) g_cnt[i] = 0;
    if (i < C3) {
        g_bns[0][i] = 0.f; g_bnq[0][i] = 0.f;
        g_bns[1][i] = 0.f; g_bnq[1][i] = 0.f;
    }
}
__global__ void csr_hist(const int* __restrict__ dst) {
    int i = blockIdx.x * blockDim.x + threadIdx.x;
    if (i < EE) atomicAdd(&g_cnt[dst[i]], 1);
}
__global__ void csr_scan_all() {
    __shared__ int wsum[32];
    __shared__ int carry_s;
    int tid = threadIdx.x, lane = tid & 31, w = tid >> 5;
    if (tid == 0) carry_s = 0;
    __syncthreads();
    for (int base = 0; base < NN; base += 1024) {
        int i = base + tid;
        int v = (i < NN) ? g_cnt[i] : 0;
        int x = v;
#pragma unroll
        for (int o = 1; o < 32; o <<= 1) {
            int t = __shfl_up_sync(0xffffffffu, x, o);
            if (lane >= o) x += t;
        }
        if (lane == 31) wsum[w] = x;
        __syncthreads();
        if (w == 0) {
            int s = wsum[lane];
#pragma unroll
            for (int o = 1; o < 32; o <<= 1) {
                int t = __shfl_up_sync(0xffffffffu, s, o);
                if (lane >= o) s += t;
            }
            wsum[lane] = s;
        }
        __syncthreads();
        int incl = x + (w > 0 ? wsum[w - 1] : 0) + carry_s;
        if (i < NN) { g_off[i] = incl - v; g_cur[i] = incl - v; }
        __syncthreads();
        if (tid == 1023) carry_s = incl;
        __syncthreads();
    }
    if (threadIdx.x == 0) g_off[NN] = EE;
}
__global__ void csr_scatter(const int* __restrict__ dst) {
    int i = blockIdx.x * blockDim.x + threadIdx.x;
    if (i < EE) {
        int p = atomicAdd(&g_cur[dst[i]], 1);
        g_eidx[p] = i;
    }
}

// ------- fused softmax + aggregation + BN-stats, layers 0/1 (el/er from g_f) -------
#define BNP (C3 + 4)
__global__ void softmax_aggr_h128(const int* __restrict__ src, int slot) {
    __shared__ float sbn[8][BNP];
    __shared__ float sbq[8][BNP];
    int tid = threadIdx.x;
    int w = tid >> 5;
    int lane = tid & 31;

    int n = (blockIdx.x * blockDim.x + tid) >> 5;
    float4 acc0 = make_float4(0.f, 0.f, 0.f, 0.f);
    float4 acc1 = acc0, acc2 = acc0;

    if (n < NN) {
        int o0 = g_off[n], o1 = g_off[n + 1];
        int deg = o1 - o0;
        const float* ern = g_f + (size_t)n * FP + 387;
        float er0 = ern[0], er1 = ern[1], er2 = ern[2];

        if (deg <= 32) {
            int sidx = 0;
            float v0 = -1e30f, v1 = -1e30f, v2 = -1e30f;
            if (lane < deg) {
                int e = g_eidx[o0 + lane];
                sidx = src[e];
                const float* els = g_f + (size_t)sidx * FP + 384;
                v0 = lrelu(els[0] + er0);
                v1 = lrelu(els[1] + er1);
                v2 = lrelu(els[2] + er2);
            }
            float m0 = wmaxf(v0), m1 = wmaxf(v1), m2 = wmaxf(v2);
            float x0 = (lane < deg) ? __expf(v0 - m0) : 0.f;
            float x1 = (lane < deg) ? __expf(v1 - m1) : 0.f;
            float x2 = (lane < deg) ? __expf(v2 - m2) : 0.f;
            float s0 = 1.f / wsumf(x0), s1 = 1.f / wsumf(x1), s2 = 1.f / wsumf(x2);
            x0 *= s0; x1 *= s1; x2 *= s2;
            for (int i = 0; i < deg; i++) {
                float a0 = __shfl_sync(0xffffffffu, x0, i);
                float a1 = __shfl_sync(0xffffffffu, x1, i);
                float a2 = __shfl_sync(0xffffffffu, x2, i);
                int s = __shfl_sync(0xffffffffu, sidx, i);
                const float* base = g_f + (size_t)s * FP + lane * 4;
                float4 w0 = *(const float4*)(base);
                float4 w1 = *(const float4*)(base + 128);
                float4 w2 = *(const float4*)(base + 256);
                acc0.x += a0 * w0.x; acc0.y += a0 * w0.y; acc0.z += a0 * w0.z; acc0.w += a0 * w0.w;
                acc1.x += a1 * w1.x; acc1.y += a1 * w1.y; acc1.z += a1 * w1.z; acc1.w += a1 * w1.w;
                acc2.x += a2 * w2.x; acc2.y += a2 * w2.y; acc2.z += a2 * w2.z; acc2.w += a2 * w2.w;
            }
        } else {
            float m0 = -1e30f, m1 = -1e30f, m2 = -1e30f;
            for (int i = o0 + lane; i < o1; i += 32) {
                int e = g_eidx[i];
                int s = src[e];
                const float* els = g_f + (size_t)s * FP + 384;
                float v0 = lrelu(els[0] + er0);
                float v1 = lrelu(els[1] + er1);
                float v2 = lrelu(els[2] + er2);
                g_e[(size_t)e * 3 + 0] = v0;
                g_e[(size_t)e * 3 + 1] = v1;
                g_e[(size_t)e * 3 + 2] = v2;
                m0 = fmaxf(m0, v0); m1 = fmaxf(m1, v1); m2 = fmaxf(m2, v2);
            }
            m0 = wmaxf(m0); m1 = wmaxf(m1); m2 = wmaxf(m2);
            float s0 = 0.f, s1 = 0.f, s2 = 0.f;
            for (int i = o0 + lane; i < o1; i += 32) {
                int e = g_eidx[i];
                float x0 = __expf(g_e[(size_t)e * 3 + 0] - m0);
                float x1 = __expf(g_e[(size_t)e * 3 + 1] - m1);
                float x2 = __expf(g_e[(size_t)e * 3 + 2] - m2);
                g_e[(size_t)e * 3 + 0] = x0;
                g_e[(size_t)e * 3 + 1] = x1;
                g_e[(size_t)e * 3 + 2] = x2;
                s0 += x0; s1 += x1; s2 += x2;
            }
            s0 = 1.f / wsumf(s0); s1 = 1.f / wsumf(s1); s2 = 1.f / wsumf(s2);
            for (int c = o0; c < o1; c += 32) {
                int cnt = min(32, o1 - c);
                int s = 0;
                float x0 = 0.f, x1 = 0.f, x2 = 0.f;
                if (lane < cnt) {
                    int e = g_eidx[c + lane];
                    s = src[e];
                    x0 = g_e[(size_t)e * 3 + 0] * s0;
                    x1 = g_e[(size_t)e * 3 + 1] * s1;
                    x2 = g_e[(size_t)e * 3 + 2] * s2;
                }
                for (int i = 0; i < cnt; i++) {
                    float a0 = __shfl_sync(0xffffffffu, x0, i);
                    float a1 = __shfl_sync(0xffffffffu, x1, i);
                    float a2 = __shfl_sync(0xffffffffu, x2, i);
                    int ss = __shfl_sync(0xffffffffu, s, i);
                    const float* base = g_f + (size_t)ss * FP + lane * 4;
                    float4 w0 = *(const float4*)(base);
                    float4 w1 = *(const float4*)(base + 128);
                    float4 w2 = *(const float4*)(base + 256);
                    acc0.x += a0 * w0.x; acc0.y += a0 * w0.y; acc0.z += a0 * w0.z; acc0.w += a0 * w0.w;
                    acc1.x += a1 * w1.x; acc1.y += a1 * w1.y; acc1.z += a1 * w1.z; acc1.w += a1 * w1.w;
                    acc2.x += a2 * w2.x; acc2.y += a2 * w2.y; acc2.z += a2 * w2.z; acc2.w += a2 * w2.w;
                }
            }
        }
        float* ob = g_out + (size_t)n * C3 + lane * 4;
        *(float4*)(ob) = acc0;
        *(float4*)(ob + 128) = acc1;
        *(float4*)(ob + 256) = acc2;
    }

    int c0 = lane * 4;
    sbn[w][c0 + 0] = acc0.x;  sbn[w][c0 + 1] = acc0.y;
    sbn[w][c0 + 2] = acc0.z;  sbn[w][c0 + 3] = acc0.w;
    sbn[w][128 + c0 + 0] = acc1.x;  sbn[w][128 + c0 + 1] = acc1.y;
    sbn[w][128 + c0 + 2] = acc1.z;  sbn[w][128 + c0 + 3] = acc1.w;
    sbn[w][256 + c0 + 0] = acc2.x;  sbn[w][256 + c0 + 1] = acc2.y;
    sbn[w][256 + c0 + 2] = acc2.z;  sbn[w][256 + c0 + 3] = acc2.w;
    sbq[w][c0 + 0] = acc0.x * acc0.x;  sbq[w][c0 + 1] = acc0.y * acc0.y;
    sbq[w][c0 + 2] = acc0.z * acc0.z;  sbq[w][c0 + 3] = acc0.w * acc0.w;
    sbq[w][128 + c0 + 0] = acc1.x * acc1.x;  sbq[w][128 + c0 + 1] = acc1.y * acc1.y;
    sbq[w][128 + c0 + 2] = acc1.z * acc1.z;  sbq[w][128 + c0 + 3] = acc1.w * acc1.w;
    sbq[w][256 + c0 + 0] = acc2.x * acc2.x;  sbq[w][256 + c0 + 1] = acc2.y * acc2.y;
    sbq[w][256 + c0 + 2] = acc2.z * acc2.z;  sbq[w][256 + c0 + 3] = acc2.w * acc2.w;
    __syncthreads();

    for (int c = tid; c < C3; c += 256) {
        float s = 0.f, q = 0.f;
#pragma unroll
        for (int ww = 0; ww < 8; ww++) { s += sbn[ww][c]; q += sbq[ww][c]; }
        atomicAdd(&g_bns[slot][c], s);
        atomicAdd(&g_bnq[slot][c], q);
    }
}

// ---------------- fused softmax + aggregation, layer 2 (el/er in cols 40/41) -------
__global__ void softmax_aggr_out40(const int* __restrict__ src, float* __restrict__ out,
                                   const float* __restrict__ b2) {
    int n = (blockIdx.x * blockDim.x + threadIdx.x) >> 5;
    int lane = threadIdx.x & 31;
    if (n >= NN) return;
    int o0 = g_off[n], o1 = g_off[n + 1];
    int deg = o1 - o0;
    float er0 = g_f[(size_t)n * OPAD + 41];
    float a0acc = 0.f, a1acc = 0.f;

    if (deg <= 32) {
        int sidx = 0;
        float v0 = -1e30f;
        if (lane < deg) {
            int e = g_eidx[o0 + lane];
            sidx = src[e];
            v0 = lrelu(g_f[(size_t)sidx * OPAD + 40] + er0);
        }
        float m0 = wmaxf(v0);
        float x0 = (lane < deg) ? __expf(v0 - m0) : 0.f;
        float s0 = 1.f / wsumf(x0);
        x0 *= s0;
        for (int i = 0; i < deg; i++) {
            float a = __shfl_sync(0xffffffffu, x0, i);
            int s = __shfl_sync(0xffffffffu, sidx, i);
            const float* fr = g_f + (size_t)s * OPAD;
            a0acc += a * fr[lane];
            if (lane < 8) a1acc += a * fr[32 + lane];
        }
    } else {
        float m0 = -1e30f;
        for (int i = o0 + lane; i < o1; i += 32) {
            int e = g_eidx[i];
            float v0 = lrelu(g_f[(size_t)src[e] * OPAD + 40] + er0);
            g_e[e] = v0;
            m0 = fmaxf(m0, v0);
        }
        m0 = wmaxf(m0);
        float s0 = 0.f;
        for (int i = o0 + lane; i < o1; i += 32) {
            int e = g_eidx[i];
            float x0 = __expf(g_e[e] - m0);
            g_e[e] = x0;
            s0 += x0;
        }
        s0 = 1.f / wsumf(s0);
        for (int c = o0; c < o1; c += 32) {
            int cnt = min(32, o1 - c);
            int s = 0;
            float x0 = 0.f;
            if (lane < cnt) {
                int e = g_eidx[c + lane];
                s = src[e];
                x0 = g_e[e] * s0;
            }
            for (int i = 0; i < cnt; i++) {
                float a = __shfl_sync(0xffffffffu, x0, i);
                int ss = __shfl_sync(0xffffffffu, s, i);
                const float* fr = g_f + (size_t)ss * OPAD;
                a0acc += a * fr[lane];
                if (lane < 8) a1acc += a * fr[32 + lane];
            }
        }
    }
    out[(size_t)n * OUTC + lane] = a0acc + b2[lane];
    if (lane < 8) out[(size_t)n * OUTC + 32 + lane] = a1acc + b2[32 + lane];
}

// ---------------- batch norm apply (tf32-rounded output) ----------------
__global__ void bn_apply_relu(const float* __restrict__ g, const float* __restrict__ be,
                              int slot) {
    int i4 = blockIdx.x * blockDim.x + threadIdx.x;
    if (i4 >= NN * 96) return;
    int c4 = (i4 - (i4 / 96) * 96) * 4;
    float4 v = ((const float4*)g_out)[i4];
    float4 r;
#pragma unroll
    for (int j = 0; j < 4; j++) {
        float vv = j == 0 ? v.x : j == 1 ? v.y : j == 2 ? v.z : v.w;
        int c = c4 + j;
        float mu = g_bns[slot][c] * (1.0f / NN);
        float var = g_bnq[slot][c] * (1.0f / NN) - mu * mu;
        float y = g[c] * (vv - mu) * rsqrtf(var + BN_EPS) + be[c];
        y = y > 0.f ? y : 0.f;
        y = wmma::__float_to_tf32(y);
        if (j == 0) r.x = y; else if (j == 1) r.y = y; else if (j == 2) r.z = y; else r.w = y;
    }
    ((float4*)g_h)[i4] = r;
}

// ---------------- orchestration ----------------
extern "C" void kernel_launch(void* const* d_in, const int* in_sizes, int n_in,
                              void* d_out, int out_size) {
    const float* x   = (const float*)d_in[0];
    const int*   src = (const int*)d_in[1];
    const int*   dst = (const int*)d_in[2];
    const float* W0  = (const float*)d_in[3];
    const float* al0 = (const float*)d_in[4];
    const float* ar0 = (const float*)d_in[5];
    const float* W1  = (const float*)d_in[7];
    const float* al1 = (const float*)d_in[8];
    const float* ar1 = (const float*)d_in[9];
    const float* W2  = (const float*)d_in[11];
    const float* al2 = (const float*)d_in[12];
    const float* ar2 = (const float*)d_in[13];
    const float* b2  = (const float*)d_in[14];
    const float* g0  = (const float*)d_in[15];
    const float* be0 = (const float*)d_in[16];
    const float* g1  = (const float*)d_in[17];
    const float* be1 = (const float*)d_in[18];
    float* out = (float*)d_out;

    float *pf = nullptr, *ph = nullptr, *pw0 = nullptr, *pw1 = nullptr, *pw2 = nullptr;
    cudaGetSymbolAddress((void**)&pf, g_f);
    cudaGetSymbolAddress((void**)&ph, g_h);
    cudaGetSymbolAddress((void**)&pw0, g_wp0);
    cudaGetSymbolAddress((void**)&pw1, g_wp1);
    cudaGetSymbolAddress((void**)&pw2, g_wp2);

    const int TB = 256;
    dim3 ggL(7, (NN + 127) / 128);           // 400 cols -> 7 tiles of 64
    dim3 gg48(1, (NN + 127) / 128);
    int warps_node = (NN * 32 + TB - 1) / TB;
    cudaStream_t s2 = g_ss.s;

    // -------- fork: side stream builds padded weights + CSR --------
    cudaEventRecord(g_ss.fork, 0);
    cudaStreamWaitEvent(s2, g_ss.fork, 0);

    wprep<<<(HID * FP + TB - 1) / TB, TB, 0, s2>>>(W0, al0, ar0, pw0, HID, C3, FP, 3, HID);
    cudaEventRecord(g_ss.join_w0, s2);
    wprep<<<(C3 * FP + TB - 1) / TB, TB, 0, s2>>>(W1, al1, ar1, pw1, C3, C3, FP, 3, HID);
    wprep<<<(C3 * OPAD + TB - 1) / TB, TB, 0, s2>>>(W2, al2, ar2, pw2, C3, OUTC, OPAD, 1, OUTC);
    csr_zero<<<(NN + TB - 1) / TB, TB, 0, s2>>>();
    csr_hist<<<(EE + TB - 1) / TB, TB, 0, s2>>>(dst);
    csr_scan_all<<<1, 1024, 0, s2>>>();
    csr_scatter<<<(EE + TB - 1) / TB, TB, 0, s2>>>(dst);
    cudaEventRecord(g_ss.join_csr, s2);

    // -------- main stream: layer 0 --------
    round_tf32<<<(NN * 32 + TB - 1) / TB, TB>>>(x, ph, NN * 32);
    cudaStreamWaitEvent(0, g_ss.join_w0, 0);
    gemm_tf32<<<ggL, TB>>>(ph, pw0, pf, NN, FP, HID, FP);

    cudaStreamWaitEvent(0, g_ss.join_csr, 0);
    softmax_aggr_h128<<<warps_node, TB>>>(src, 0);
    bn_apply_relu<<<(NN * 96 + TB - 1) / TB, TB>>>(g0, be0, 0);

    // ---------- layer 1 ----------
    gemm_tf32<<<ggL, TB>>>(ph, pw1, pf, NN, FP, C3, FP);
    softmax_aggr_h128<<<warps_node, TB>>>(src, 1);
    bn_apply_relu<<<(NN * 96 + TB - 1) / TB, TB>>>(g1, be1, 1);

    // ---------- layer 2 ----------
    gemm_tf32<<<gg48, TB>>>(ph, pw2, pf, NN, OPAD, C3, OPAD);
    softmax_aggr_out40<<<warps_node, TB>>>(src, out, b2);
}

// round 17
// speedup vs baseline: 1.0722x; 1.0722x over previous
#include <cuda_runtime.h>
#include <cuda_bf16.h>
#include <mma.h>
#include <cstdint>

using namespace nvcuda;

#define NN 50000
#define EE 800000
#define C3 384
#define HID 128
#define OUTC 40
#define OPAD 48
#define BN_EPS 1e-5f
#define SLOPE 0.2f
#define HALF0 25088                  // 196 row-blocks of 128
#define HALF1 (NN - HALF0)           // 24912 -> 195 blocks

// ---------------- scratch ----------------
__device__ __align__(128) float g_f[(size_t)NN * C3];
__device__ __align__(128) float g_h[(size_t)NN * C3];
__device__ __align__(128) float g_out[(size_t)NN * C3];
__device__ __align__(128) float g_wr0[HID * C3];
__device__ __align__(128) float g_wr1[C3 * C3];
__device__ __align__(128) float g_wr2[C3 * OPAD];
__device__ __align__(128) float g_el[NN * 3];
__device__ __align__(128) float g_er[NN * 3];
__device__ __align__(128) float g_e[(size_t)EE * 3];
__device__ __align__(128) float g_bnsum[C3];
__device__ __align__(128) float g_bnsq[C3];
__device__ __align__(128) int g_cnt[NN];
__device__ __align__(128) int g_off[NN + 1];
__device__ __align__(128) int g_cur[NN];
__device__ __align__(128) int g_eidx[EE];

// side stream + events (host objects only, created once)
struct SideStream {
    cudaStream_t s = nullptr;
    cudaEvent_t fork = nullptr, join_csr = nullptr, join_w0 = nullptr;
    cudaEvent_t evG0 = nullptr, evA0 = nullptr, evG1 = nullptr, evA1 = nullptr;
    SideStream() {
        cudaStreamCreateWithFlags(&s, cudaStreamNonBlocking);
        cudaEventCreateWithFlags(&fork, cudaEventDisableTiming);
        cudaEventCreateWithFlags(&join_csr, cudaEventDisableTiming);
        cudaEventCreateWithFlags(&join_w0, cudaEventDisableTiming);
        cudaEventCreateWithFlags(&evG0, cudaEventDisableTiming);
        cudaEventCreateWithFlags(&evA0, cudaEventDisableTiming);
        cudaEventCreateWithFlags(&evG1, cudaEventDisableTiming);
        cudaEventCreateWithFlags(&evA1, cudaEventDisableTiming);
    }
};
static SideStream g_ss;

__device__ __forceinline__ float lrelu(float v) { return v > 0.f ? v : SLOPE * v; }
__device__ __forceinline__ float wmaxf(float v) {
#pragma unroll
    for (int o = 16; o; o >>= 1) v = fmaxf(v, __shfl_xor_sync(0xffffffffu, v, o));
    return v;
}
__device__ __forceinline__ float wsumf(float v) {
#pragma unroll
    for (int o = 16; o; o >>= 1) v += __shfl_xor_sync(0xffffffffu, v, o);
    return v;
}
__device__ __forceinline__ void cp16(void* dst, const void* src, bool pred) {
    uint32_t d = (uint32_t)__cvta_generic_to_shared(dst);
    int sz = pred ? 16 : 0;
    asm volatile("cp.async.cg.shared.global [%0], [%1], 16, %2;\n"
                 :: "r"(d), "l"(src), "r"(sz));
}

// ---------------- tf32 rounding pass ----------------
__global__ void round_tf32(const float* __restrict__ in, float* __restrict__ out, int n4) {
    int i = blockIdx.x * blockDim.x + threadIdx.x;
    if (i >= n4) return;
    float4 v = ((const float4*)in)[i];
    v.x = wmma::__float_to_tf32(v.x);
    v.y = wmma::__float_to_tf32(v.y);
    v.z = wmma::__float_to_tf32(v.z);
    v.w = wmma::__float_to_tf32(v.w);
    ((float4*)out)[i] = v;
}

// ---- tf32 GEMM, 3-stage cp.async, 128x64 tile, warp tile 32x32 ---------------------
#define BM 128
#define BNT 64
#define BKK 16
#define APITCH (BKK + 4)
#define BPITCH (BNT + 4)
#define ASTAGE (BM * APITCH)
#define BSTAGE (BKK * BPITCH)

__global__ void __launch_bounds__(256) gemm_tf32(const float* __restrict__ A,
                                                 const float* __restrict__ B,
                                                 float* __restrict__ C,
                                                 int M, int N, int K, int ldc) {
    __shared__ float As[3][ASTAGE];
    __shared__ float Bs[3][BSTAGE];

    const int tid = threadIdx.x;
    const int wid = tid >> 5;
    const int warp_m = wid >> 1;
    const int warp_n = wid & 1;
    const int row0 = blockIdx.y * BM;
    const int col0 = blockIdx.x * BNT;

    wmma::fragment<wmma::accumulator, 16, 16, 8, float> acc[2][2];
#pragma unroll
    for (int i = 0; i < 2; i++)
#pragma unroll
        for (int j = 0; j < 2; j++) wmma::fill_fragment(acc[i][j], 0.f);

    auto load_tile = [&](int k0, int buf) {
        float* Ab = As[buf];
        float* Bb = Bs[buf];
#pragma unroll
        for (int t = 0; t < 2; t++) {
            int idx = tid + t * 256;
            int r = idx >> 2;
            int c4 = (idx & 3) * 4;
            cp16(&Ab[r * APITCH + c4], &A[(size_t)(row0 + r) * K + k0 + c4], (row0 + r) < M);
        }
        {
            int r = tid >> 4;
            int c4 = (tid & 15) * 4;
            cp16(&Bb[r * BPITCH + c4], &B[(size_t)(k0 + r) * N + col0 + c4], (col0 + c4) < N);
        }
        asm volatile("cp.async.commit_group;\n");
    };

    const int KT = K / BKK;
    load_tile(0, 0);
    if (KT > 1) load_tile(BKK, 1);

    int buf = 0;
    for (int kt = 0; kt < KT; kt++) {
        asm volatile("cp.async.wait_group 1;\n");
        __syncthreads();
        float* Ab = As[buf];
        float* Bb = Bs[buf];
#pragma unroll
        for (int kk = 0; kk < BKK; kk += 8) {
            wmma::fragment<wmma::matrix_a, 16, 16, 8, wmma::precision::tf32, wmma::row_major> af[2];
            wmma::fragment<wmma::matrix_b, 16, 16, 8, wmma::precision::tf32, wmma::row_major> bf[2];
#pragma unroll
            for (int i = 0; i < 2; i++)
                wmma::load_matrix_sync(af[i], &Ab[(warp_m * 32 + i * 16) * APITCH + kk], APITCH);
#pragma unroll
            for (int j = 0; j < 2; j++)
                wmma::load_matrix_sync(bf[j], &Bb[kk * BPITCH + warp_n * 32 + j * 16], BPITCH);
#pragma unroll
            for (int i = 0; i < 2; i++)
#pragma unroll
                for (int j = 0; j < 2; j++)
                    wmma::mma_sync(acc[i][j], af[i], bf[j], acc[i][j]);
        }
        if (kt + 2 < KT) load_tile((kt + 2) * BKK, (kt + 2) % 3);
        else asm volatile("cp.async.commit_group;\n");
        buf = (buf + 1) % 3;
    }

#pragma unroll
    for (int i = 0; i < 2; i++) {
        int gr = row0 + warp_m * 32 + i * 16;
        if (gr >= M) continue;
#pragma unroll
        for (int j = 0; j < 2; j++) {
            int gc = col0 + warp_n * 32 + j * 16;
            if (gc + 16 <= ldc)
                wmma::store_matrix_sync(&C[(size_t)gr * ldc + gc], acc[i][j], ldc, wmma::mem_row_major);
        }
    }
}

// ------- attention scores over node range [n0, n1); zeroes BN accum when n0==0 ------
__global__ void attn_scores(const float* __restrict__ al, const float* __restrict__ ar,
                            int nh, int d, int rs, int n0, int n1) {
    if (n0 == 0 && blockIdx.x == 0) {
        for (int c = threadIdx.x; c < C3; c += blockDim.x) {
            g_bnsum[c] = 0.f;
            g_bnsq[c] = 0.f;
        }
    }
    int gw = (blockIdx.x * blockDim.x + threadIdx.x) >> 5;
    int lane = threadIdx.x & 31;
    if (gw >= (n1 - n0) * nh) return;
    int n = n0 + gw / nh, h = gw - (gw / nh) * nh;
    const float* fr = g_f + (size_t)n * rs + (size_t)h * d;
    float sl = 0.f, sr = 0.f;
    for (int i = lane * 4; i < d; i += 128) {
        float4 v = *(const float4*)&fr[i];
        float4 a4 = *(const float4*)&al[h * d + i];
        float4 r4 = *(const float4*)&ar[h * d + i];
        sl += v.x * a4.x + v.y * a4.y + v.z * a4.z + v.w * a4.w;
        sr += v.x * r4.x + v.y * r4.y + v.z * r4.z + v.w * r4.w;
    }
    sl = wsumf(sl);
    sr = wsumf(sr);
    if (lane == 0) { g_el[n * nh + h] = sl; g_er[n * nh + h] = sr; }
}

// ---------------- CSR build ----------------
__global__ void csr_zero() {
    int i = blockIdx.x * blockDim.x + threadIdx.x;
    if (i < NN) g_cnt[i] = 0;
}
__global__ void csr_hist(const int* __restrict__ dst) {
    int i = blockIdx.x * blockDim.x + threadIdx.x;
    if (i < EE) atomicAdd(&g_cnt[dst[i]], 1);
}
__global__ void csr_scan_all() {
    __shared__ int wsum[32];
    __shared__ int carry_s;
    int tid = threadIdx.x, lane = tid & 31, w = tid >> 5;
    if (tid == 0) carry_s = 0;
    __syncthreads();
    for (int base = 0; base < NN; base += 1024) {
        int i = base + tid;
        int v = (i < NN) ? g_cnt[i] : 0;
        int x = v;
#pragma unroll
        for (int o = 1; o < 32; o <<= 1) {
            int t = __shfl_up_sync(0xffffffffu, x, o);
            if (lane >= o) x += t;
        }
        if (lane == 31) wsum[w] = x;
        __syncthreads();
        if (w == 0) {
            int s = wsum[lane];
#pragma unroll
            for (int o = 1; o < 32; o <<= 1) {
                int t = __shfl_up_sync(0xffffffffu, s, o);
                if (lane >= o) s += t;
            }
            wsum[lane] = s;
        }
        __syncthreads();
        int incl = x + (w > 0 ? wsum[w - 1] : 0) + carry_s;
        if (i < NN) { g_off[i] = incl - v; g_cur[i] = incl - v; }
        __syncthreads();
        if (tid == 1023) carry_s = incl;
        __syncthreads();
    }
    if (threadIdx.x == 0) g_off[NN] = EE;
}
__global__ void csr_scatter(const int* __restrict__ dst) {
    int i = blockIdx.x * blockDim.x + threadIdx.x;
    if (i < EE) {
        int p = atomicAdd(&g_cur[dst[i]], 1);
        g_eidx[p] = i;
    }
}

// ------- fused softmax + aggregation + BN-stats (atomic-free), layers 0/1 ----------
#define BNP (C3 + 4)
__global__ void softmax_aggr_h128(const int* __restrict__ src) {
    __shared__ float sbn[8][BNP];
    __shared__ float sbq[8][BNP];
    int tid = threadIdx.x;
    int w = tid >> 5;
    int lane = tid & 31;

    int n = (blockIdx.x * blockDim.x + tid) >> 5;
    float4 acc0 = make_float4(0.f, 0.f, 0.f, 0.f);
    float4 acc1 = acc0, acc2 = acc0;

    if (n < NN) {
        int o0 = g_off[n], o1 = g_off[n + 1];
        int deg = o1 - o0;
        float er0 = g_er[n * 3 + 0], er1 = g_er[n * 3 + 1], er2 = g_er[n * 3 + 2];

        if (deg <= 32) {
            int sidx = 0;
            float v0 = -1e30f, v1 = -1e30f, v2 = -1e30f;
            if (lane < deg) {
                int e = g_eidx[o0 + lane];
                sidx = src[e];
                v0 = lrelu(g_el[sidx * 3 + 0] + er0);
                v1 = lrelu(g_el[sidx * 3 + 1] + er1);
                v2 = lrelu(g_el[sidx * 3 + 2] + er2);
            }
            float m0 = wmaxf(v0), m1 = wmaxf(v1), m2 = wmaxf(v2);
            float x0 = (lane < deg) ? __expf(v0 - m0) : 0.f;
            float x1 = (lane < deg) ? __expf(v1 - m1) : 0.f;
            float x2 = (lane < deg) ? __expf(v2 - m2) : 0.f;
            float s0 = 1.f / wsumf(x0), s1 = 1.f / wsumf(x1), s2 = 1.f / wsumf(x2);
            x0 *= s0; x1 *= s1; x2 *= s2;
            for (int i = 0; i < deg; i++) {
                float a0 = __shfl_sync(0xffffffffu, x0, i);
                float a1 = __shfl_sync(0xffffffffu, x1, i);
                float a2 = __shfl_sync(0xffffffffu, x2, i);
                int s = __shfl_sync(0xffffffffu, sidx, i);
                const float* base = g_f + (size_t)s * C3 + lane * 4;
                float4 w0 = *(const float4*)(base);
                float4 w1 = *(const float4*)(base + 128);
                float4 w2 = *(const float4*)(base + 256);
                acc0.x += a0 * w0.x; acc0.y += a0 * w0.y; acc0.z += a0 * w0.z; acc0.w += a0 * w0.w;
                acc1.x += a1 * w1.x; acc1.y += a1 * w1.y; acc1.z += a1 * w1.z; acc1.w += a1 * w1.w;
                acc2.x += a2 * w2.x; acc2.y += a2 * w2.y; acc2.z += a2 * w2.z; acc2.w += a2 * w2.w;
            }
        } else {
            float m0 = -1e30f, m1 = -1e30f, m2 = -1e30f;
            for (int i = o0 + lane; i < o1; i += 32) {
                int e = g_eidx[i];
                int s = src[e];
                float v0 = lrelu(g_el[s * 3 + 0] + er0);
                float v1 = lrelu(g_el[s * 3 + 1] + er1);
                float v2 = lrelu(g_el[s * 3 + 2] + er2);
                g_e[(size_t)e * 3 + 0] = v0;
                g_e[(size_t)e * 3 + 1] = v1;
                g_e[(size_t)e * 3 + 2] = v2;
                m0 = fmaxf(m0, v0); m1 = fmaxf(m1, v1); m2 = fmaxf(m2, v2);
            }
            m0 = wmaxf(m0); m1 = wmaxf(m1); m2 = wmaxf(m2);
            float s0 = 0.f, s1 = 0.f, s2 = 0.f;
            for (int i = o0 + lane; i < o1; i += 32) {
                int e = g_eidx[i];
                float x0 = __expf(g_e[(size_t)e * 3 + 0] - m0);
                float x1 = __expf(g_e[(size_t)e * 3 + 1] - m1);
                float x2 = __expf(g_e[(size_t)e * 3 + 2] - m2);
                g_e[(size_t)e * 3 + 0] = x0;
                g_e[(size_t)e * 3 + 1] = x1;
                g_e[(size_t)e * 3 + 2] = x2;
                s0 += x0; s1 += x1; s2 += x2;
            }
            s0 = 1.f / wsumf(s0); s1 = 1.f / wsumf(s1); s2 = 1.f / wsumf(s2);
            for (int c = o0; c < o1; c += 32) {
                int cnt = min(32, o1 - c);
                int s = 0;
                float x0 = 0.f, x1 = 0.f, x2 = 0.f;
                if (lane < cnt) {
                    int e = g_eidx[c + lane];
                    s = src[e];
                    x0 = g_e[(size_t)e * 3 + 0] * s0;
                    x1 = g_e[(size_t)e * 3 + 1] * s1;
                    x2 = g_e[(size_t)e * 3 + 2] * s2;
                }
                for (int i = 0; i < cnt; i++) {
                    float a0 = __shfl_sync(0xffffffffu, x0, i);
                    float a1 = __shfl_sync(0xffffffffu, x1, i);
                    float a2 = __shfl_sync(0xffffffffu, x2, i);
                    int ss = __shfl_sync(0xffffffffu, s, i);
                    const float* base = g_f + (size_t)ss * C3 + lane * 4;
                    float4 w0 = *(const float4*)(base);
                    float4 w1 = *(const float4*)(base + 128);
                    float4 w2 = *(const float4*)(base + 256);
                    acc0.x += a0 * w0.x; acc0.y += a0 * w0.y; acc0.z += a0 * w0.z; acc0.w += a0 * w0.w;
                    acc1.x += a1 * w1.x; acc1.y += a1 * w1.y; acc1.z += a1 * w1.z; acc1.w += a1 * w1.w;
                    acc2.x += a2 * w2.x; acc2.y += a2 * w2.y; acc2.z += a2 * w2.z; acc2.w += a2 * w2.w;
                }
            }
        }
        float* ob = g_out + (size_t)n * C3 + lane * 4;
        *(float4*)(ob) = acc0;
        *(float4*)(ob + 128) = acc1;
        *(float4*)(ob + 256) = acc2;
    }

    int c0 = lane * 4;
    sbn[w][c0 + 0] = acc0.x;  sbn[w][c0 + 1] = acc0.y;
    sbn[w][c0 + 2] = acc0.z;  sbn[w][c0 + 3] = acc0.w;
    sbn[w][128 + c0 + 0] = acc1.x;  sbn[w][128 + c0 + 1] = acc1.y;
    sbn[w][128 + c0 + 2] = acc1.z;  sbn[w][128 + c0 + 3] = acc1.w;
    sbn[w][256 + c0 + 0] = acc2.x;  sbn[w][256 + c0 + 1] = acc2.y;
    sbn[w][256 + c0 + 2] = acc2.z;  sbn[w][256 + c0 + 3] = acc2.w;
    sbq[w][c0 + 0] = acc0.x * acc0.x;  sbq[w][c0 + 1] = acc0.y * acc0.y;
    sbq[w][c0 + 2] = acc0.z * acc0.z;  sbq[w][c0 + 3] = acc0.w * acc0.w;
    sbq[w][128 + c0 + 0] = acc1.x * acc1.x;  sbq[w][128 + c0 + 1] = acc1.y * acc1.y;
    sbq[w][128 + c0 + 2] = acc1.z * acc1.z;  sbq[w][128 + c0 + 3] = acc1.w * acc1.w;
    sbq[w][256 + c0 + 0] = acc2.x * acc2.x;  sbq[w][256 + c0 + 1] = acc2.y * acc2.y;
    sbq[w][256 + c0 + 2] = acc2.z * acc2.z;  sbq[w][256 + c0 + 3] = acc2.w * acc2.w;
    __syncthreads();

    for (int c = tid; c < C3; c += 256) {
        float s = 0.f, q = 0.f;
#pragma unroll
        for (int ww = 0; ww < 8; ww++) { s += sbn[ww][c]; q += sbq[ww][c]; }
        atomicAdd(&g_bnsum[c], s);
        atomicAdd(&g_bnsq[c], q);
    }
}

// ---------------- fused softmax + aggregation, layer 2 ----------------
__global__ void softmax_aggr_out40(const int* __restrict__ src, float* __restrict__ out,
                                   const float* __restrict__ b2) {
    int n = (blockIdx.x * blockDim.x + threadIdx.x) >> 5;
    int lane = threadIdx.x & 31;
    if (n >= NN) return;
    int o0 = g_off[n], o1 = g_off[n + 1];
    int deg = o1 - o0;
    float er0 = g_er[n];
    float a0acc = 0.f, a1acc = 0.f;

    if (deg <= 32) {
        int sidx = 0;
        float v0 = -1e30f;
        if (lane < deg) {
            int e = g_eidx[o0 + lane];
            sidx = src[e];
            v0 = lrelu(g_el[sidx] + er0);
        }
        float m0 = wmaxf(v0);
        float x0 = (lane < deg) ? __expf(v0 - m0) : 0.f;
        float s0 = 1.f / wsumf(x0);
        x0 *= s0;
        for (int i = 0; i < deg; i++) {
            float a = __shfl_sync(0xffffffffu, x0, i);
            int s = __shfl_sync(0xffffffffu, sidx, i);
            const float* fr = g_f + (size_t)s * OPAD;
            a0acc += a * fr[lane];
            if (lane < 8) a1acc += a * fr[32 + lane];
        }
    } else {
        float m0 = -1e30f;
        for (int i = o0 + lane; i < o1; i += 32) {
            int e = g_eidx[i];
            float v0 = lrelu(g_el[src[e]] + er0);
            g_e[e] = v0;
            m0 = fmaxf(m0, v0);
        }
        m0 = wmaxf(m0);
        float s0 = 0.f;
        for (int i = o0 + lane; i < o1; i += 32) {
            int e = g_eidx[i];
            float x0 = __expf(g_e[e] - m0);
            g_e[e] = x0;
            s0 += x0;
        }
        s0 = 1.f / wsumf(s0);
        for (int c = o0; c < o1; c += 32) {
            int cnt = min(32, o1 - c);
            int s = 0;
            float x0 = 0.f;
            if (lane < cnt) {
                int e = g_eidx[c + lane];
                s = src[e];
                x0 = g_e[e] * s0;
            }
            for (int i = 0; i < cnt; i++) {
                float a = __shfl_sync(0xffffffffu, x0, i);
                int ss = __shfl_sync(0xffffffffu, s, i);
                const float* fr = g_f + (size_t)ss * OPAD;
                a0acc += a * fr[lane];
                if (lane < 8) a1acc += a * fr[32 + lane];
            }
        }
    }
    out[(size_t)n * OUTC + lane] = a0acc + b2[lane];
    if (lane < 8) out[(size_t)n * OUTC + 32 + lane] = a1acc + b2[32 + lane];
}

// ---------------- batch norm apply (tf32-rounded output) ----------------
__global__ void bn_apply_relu(const float* __restrict__ g, const float* __restrict__ be) {
    int i4 = blockIdx.x * blockDim.x + threadIdx.x;
    if (i4 >= NN * 96) return;
    int c4 = (i4 - (i4 / 96) * 96) * 4;
    float4 v = ((const float4*)g_out)[i4];
    float4 r;
#pragma unroll
    for (int j = 0; j < 4; j++) {
        float vv = j == 0 ? v.x : j == 1 ? v.y : j == 2 ? v.z : v.w;
        int c = c4 + j;
        float mu = g_bnsum[c] * (1.0f / NN);
        float var = g_bnsq[c] * (1.0f / NN) - mu * mu;
        float y = g[c] * (vv - mu) * rsqrtf(var + BN_EPS) + be[c];
        y = y > 0.f ? y : 0.f;
        y = wmma::__float_to_tf32(y);
        if (j == 0) r.x = y; else if (j == 1) r.y = y; else if (j == 2) r.z = y; else r.w = y;
    }
    ((float4*)g_h)[i4] = r;
}

// ---------------- orchestration ----------------
extern "C" void kernel_launch(void* const* d_in, const int* in_sizes, int n_in,
                              void* d_out, int out_size) {
    const float* x   = (const float*)d_in[0];
    const int*   src = (const int*)d_in[1];
    const int*   dst = (const int*)d_in[2];
    const float* W0  = (const float*)d_in[3];
    const float* al0 = (const float*)d_in[4];
    const float* ar0 = (const float*)d_in[5];
    const float* W1  = (const float*)d_in[7];
    const float* al1 = (const float*)d_in[8];
    const float* ar1 = (const float*)d_in[9];
    const float* W2  = (const float*)d_in[11];
    const float* al2 = (const float*)d_in[12];
    const float* ar2 = (const float*)d_in[13];
    const float* b2  = (const float*)d_in[14];
    const float* g0  = (const float*)d_in[15];
    const float* be0 = (const float*)d_in[16];
    const float* g1  = (const float*)d_in[17];
    const float* be1 = (const float*)d_in[18];
    float* out = (float*)d_out;

    float *pf = nullptr, *ph = nullptr, *pw0 = nullptr, *pw1 = nullptr, *pw2 = nullptr;
    cudaGetSymbolAddress((void**)&pf, g_f);
    cudaGetSymbolAddress((void**)&ph, g_h);
    cudaGetSymbolAddress((void**)&pw0, g_wr0);
    cudaGetSymbolAddress((void**)&pw1, g_wr1);
    cudaGetSymbolAddress((void**)&pw2, g_wr2);

    const int TB = 256;
    dim3 ggH0(6, HALF0 / 128);               // rows [0, 25088)
    dim3 ggH1(6, (HALF1 + 127) / 128);       // rows [25088, 50000)
    dim3 gg48(1, (NN + 127) / 128);
    int warps_node = (NN * 32 + TB - 1) / TB;
    int aw0 = (HALF0 * 3 * 32 + TB - 1) / TB;
    int aw1 = (HALF1 * 3 * 32 + TB - 1) / TB;
    cudaStream_t s2 = g_ss.s;

    // -------- fork: side stream rounds weights then builds CSR --------
    cudaEventRecord(g_ss.fork, 0);
    cudaStreamWaitEvent(s2, g_ss.fork, 0);

    round_tf32<<<(HID * C3 / 4 + TB - 1) / TB, TB, 0, s2>>>(W0, pw0, HID * C3 / 4);
    cudaEventRecord(g_ss.join_w0, s2);
    round_tf32<<<(C3 * C3 / 4 + TB - 1) / TB, TB, 0, s2>>>(W1, pw1, C3 * C3 / 4);
    round_tf32<<<(C3 * OUTC / 4 + TB - 1) / TB, TB, 0, s2>>>(W2, pw2, C3 * OUTC / 4);
    csr_zero<<<(NN + TB - 1) / TB, TB, 0, s2>>>();
    csr_hist<<<(EE + TB - 1) / TB, TB, 0, s2>>>(dst);
    csr_scan_all<<<1, 1024, 0, s2>>>();
    csr_scatter<<<(EE + TB - 1) / TB, TB, 0, s2>>>(dst);
    cudaEventRecord(g_ss.join_csr, s2);

    // -------- layer 0: split GEMM; attn(half0) on side overlaps gemm(half1) --------
    round_tf32<<<(NN * 32 + TB - 1) / TB, TB>>>(x, ph, NN * 32);
    cudaStreamWaitEvent(0, g_ss.join_w0, 0);
    gemm_tf32<<<ggH0, TB>>>(ph, pw0, pf, HALF0, C3, HID, C3);
    cudaEventRecord(g_ss.evG0, 0);
    gemm_tf32<<<ggH1, TB>>>(ph + (size_t)HALF0 * HID, pw0, pf + (size_t)HALF0 * C3,
                            HALF1, C3, HID, C3);
    attn_scores<<<aw1, TB>>>(al0, ar0, 3, HID, C3, HALF0, NN);

    cudaStreamWaitEvent(s2, g_ss.evG0, 0);
    attn_scores<<<aw0, TB, 0, s2>>>(al0, ar0, 3, HID, C3, 0, HALF0);
    cudaEventRecord(g_ss.evA0, s2);

    cudaStreamWaitEvent(0, g_ss.join_csr, 0);
    cudaStreamWaitEvent(0, g_ss.evA0, 0);
    softmax_aggr_h128<<<warps_node, TB>>>(src);
    bn_apply_relu<<<(NN * 96 + TB - 1) / TB, TB>>>(g0, be0);

    // -------- layer 1: same split --------
    gemm_tf32<<<ggH0, TB>>>(ph, pw1, pf, HALF0, C3, C3, C3);
    cudaEventRecord(g_ss.evG1, 0);
    gemm_tf32<<<ggH1, TB>>>(ph + (size_t)HALF0 * C3, pw1, pf + (size_t)HALF0 * C3,
                            HALF1, C3, C3, C3);
    attn_scores<<<aw1, TB>>>(al1, ar1, 3, HID, C3, HALF0, NN);

    cudaStreamWaitEvent(s2, g_ss.evG1, 0);
    attn_scores<<<aw0, TB, 0, s2>>>(al1, ar1, 3, HID, C3, 0, HALF0);
    cudaEventRecord(g_ss.evA1, s2);

    cudaStreamWaitEvent(0, g_ss.evA1, 0);
    softmax_aggr_h128<<<warps_node, TB>>>(src);
    bn_apply_relu<<<(NN * 96 + TB - 1) / TB, TB>>>(g1, be1);

    // -------- layer 2 (unsplit; C padded to stride 48) --------
    gemm_tf32<<<gg48, TB>>>(ph, pw2, pf, NN, OUTC, C3, OPAD);
    attn_scores<<<(NN * 32 + TB - 1) / TB, TB>>>(al2, ar2, 1, OUTC, OPAD, 0, NN);
    softmax_aggr_out40<<<warps_node, TB>>>(src, out, b2);
}